// round 10
// baseline (speedup 1.0000x reference)
#include <cuda_runtime.h>

#define BN   4
#define LL   512
#define HH   768
#define HSZ  64
#define NOUT 16
#define NTOK (BN*LL)      // 2048
#define NP   131328       // L*(L+1)/2
#define NKQ  16           // split-K factor
#define KQ   (HH/NKQ)     // 48

// scratch (allocation-free rule: __device__ globals)
__device__ float g_part[NKQ*NTOK*128]; // 16 MB split-K partials [kq][tok][n]
__device__ float g_q[NTOK*HSZ];        // 512 KB
__device__ float g_k[NTOK*HSZ];        // 512 KB
__device__ float g_A[NTOK*NOUT];       // 128 KB
__device__ float g_E[NTOK*NOUT];       // 128 KB

// ---------------------------------------------------------------------------
// Kernel 1: split-K partial GEMM, LDS:FMA-balanced shape.
// 128-thread blocks; tile = 64 tokens x 128 cols (q|k); per-thread 8x8.
// Per kd: 4 LDS.128 (64 B) : 64 FMA per thread -> smem crossbar and FMA pipe
// co-saturate. Grid = 32 token-tiles x 16 K-slices = 512 blocks.
// ---------------------------------------------------------------------------
__global__ __launch_bounds__(128) void proj_partial_kernel(
    const float* __restrict__ x,
    const float* __restrict__ Wq,
    const float* __restrict__ Wk)
{
    __shared__ float xs[16][68];     // [k][token]
    __shared__ float ws[16][128];    // [k][n] n<64 -> Wq col else Wk col

    const int tid = threadIdx.x;
    const int tt  = blockIdx.x & 31;           // token tile (64 tokens)
    const int kq  = blockIdx.x >> 5;           // K slice
    const int t0  = tt * 64;
    const int k0  = kq * KQ;

    const int n0 = (tid & 15) * 8;             // 8 cols
    const int m0 = (tid >> 4) * 8;             // 8 tokens

    float acc[8][8];
    #pragma unroll
    for (int i = 0; i < 8; i++)
        #pragma unroll
        for (int j = 0; j < 8; j++) acc[i][j] = 0.f;

    for (int kk = k0; kk < k0 + KQ; kk += 16) {
        #pragma unroll
        for (int p = 0; p < 8; p++) {
            int e = tid + p * 128;             // 1024 = 64 tok x 16 d
            int tok = e >> 4, d = e & 15;
            xs[d][tok] = x[(t0 + tok) * HH + kk + d];
        }
        #pragma unroll
        for (int p = 0; p < 16; p++) {
            int e = tid + p * 128;             // 2048 = 128 n x 16 d
            int n = e & 127, d = e >> 7;
            ws[d][n] = (n < 64) ? Wq[(kk + d) * HSZ + n]
                                : Wk[(kk + d) * HSZ + (n - 64)];
        }
        __syncthreads();
        #pragma unroll
        for (int kd = 0; kd < 16; kd++) {
            float4 a0 = *(const float4*)&xs[kd][m0];
            float4 a1 = *(const float4*)&xs[kd][m0 + 4];
            float4 w0 = *(const float4*)&ws[kd][n0];
            float4 w1 = *(const float4*)&ws[kd][n0 + 4];
            float am[8] = {a0.x, a0.y, a0.z, a0.w, a1.x, a1.y, a1.z, a1.w};
            float wn[8] = {w0.x, w0.y, w0.z, w0.w, w1.x, w1.y, w1.z, w1.w};
            #pragma unroll
            for (int i = 0; i < 8; i++)
                #pragma unroll
                for (int j = 0; j < 8; j++) acc[i][j] += am[i] * wn[j];
        }
        __syncthreads();
    }

    #pragma unroll
    for (int i = 0; i < 8; i++) {
        float* gp = g_part + ((size_t)kq * NTOK + t0 + m0 + i) * 128 + n0;
        *(float4*)&gp[0] = make_float4(acc[i][0], acc[i][1], acc[i][2], acc[i][3]);
        *(float4*)&gp[4] = make_float4(acc[i][4], acc[i][5], acc[i][6], acc[i][7]);
    }
}

// ---------------------------------------------------------------------------
// Kernel 2: reduce split-K partials + bias -> g_q/g_k, then A/E tables.
// A[s,o] = q[s]@Wb[0:64] + bb
// E[e,o] = k[e]@(Wb[64:128]+Wb[192:256]) + q[e]@Wb[128:192]
// ---------------------------------------------------------------------------
__global__ __launch_bounds__(256) void reduce_ae_kernel(
    const float* __restrict__ bq, const float* __restrict__ bk,
    const float* __restrict__ bb, const float* __restrict__ Wb)
{
    __shared__ float Wbs[256 * NOUT];
    __shared__ float sQK[32][132];
    __shared__ float bbs[NOUT];
    __shared__ float bqs[HSZ], bks[HSZ];

    const int tid = threadIdx.x;
    const int t0  = blockIdx.x * 32;

    #pragma unroll
    for (int p = 0; p < 16; p++)
        Wbs[tid + p * 256] = Wb[tid + p * 256];
    if (tid < NOUT) bbs[tid] = bb[tid];
    if (tid < HSZ)  { bqs[tid] = bq[tid]; bks[tid] = bk[tid]; }
    __syncthreads();

    const float4* gp4 = (const float4*)g_part;
    #pragma unroll
    for (int p = 0; p < 4; p++) {
        int e  = tid + p * 256;
        int tok = e >> 5, n4 = e & 31;
        size_t gi = (size_t)(t0 + tok) * 32 + n4;
        float4 v = make_float4(0.f, 0.f, 0.f, 0.f);
        #pragma unroll
        for (int q = 0; q < NKQ; q++) {
            float4 pv = gp4[(size_t)q * NTOK * 32 + gi];
            v.x += pv.x; v.y += pv.y; v.z += pv.z; v.w += pv.w;
        }
        int n = n4 * 4;
        if (n < 64) { v.x += bqs[n]; v.y += bqs[n+1]; v.z += bqs[n+2]; v.w += bqs[n+3]; }
        else        { v.x += bks[n-64]; v.y += bks[n-63]; v.z += bks[n-62]; v.w += bks[n-61]; }
        *(float4*)&sQK[tok][n] = v;
        int tok_g = t0 + tok;
        if (n4 < 16) ((float4*)(g_q + tok_g * HSZ))[n4]      = v;
        else         ((float4*)(g_k + tok_g * HSZ))[n4 - 16] = v;
    }
    __syncthreads();

    // A table: 32 tok x 16 o (warp-uniform)
    #pragma unroll
    for (int p = 0; p < 2; p++) {
        int e2   = tid + p * 256;
        int tokL = e2 >> 4;
        int o    = e2 & 15;
        float a = bbs[o];
        #pragma unroll 8
        for (int h = 0; h < 64; h++)
            a += sQK[tokL][h] * Wbs[h * NOUT + o];
        g_A[(t0 + tokL) * NOUT + o] = a;
    }
    // E table
    #pragma unroll
    for (int p = 0; p < 2; p++) {
        int e2   = tid + p * 256;
        int tokL = e2 >> 4;
        int o    = e2 & 15;
        float a = 0.f;
        #pragma unroll 8
        for (int h = 0; h < 64; h++) {
            a += sQK[tokL][64 + h] * (Wbs[(64 + h) * NOUT + o] + Wbs[(192 + h) * NOUT + o]);
            a += sQK[tokL][h]      *  Wbs[(128 + h) * NOUT + o];
        }
        g_E[(t0 + tokL) * NOUT + o] = a;
    }
}

// ---------------------------------------------------------------------------
// Kernel 3: FUSED score + scatter (R9, unchanged). One block per 64x64 tile;
// below-diagonal tiles exit; output streamed straight from shared.
// ---------------------------------------------------------------------------
__global__ __launch_bounds__(256) void score_scatter_kernel(float* __restrict__ out)
{
    const int bx = blockIdx.x;   // e tile
    const int by = blockIdx.y;   // s tile
    if (by > bx) return;
    const int b  = blockIdx.z;

    __shared__ float  qs[64][68];
    __shared__ float  ks[64][68];
    __shared__ float  Ss[64][65];
    __shared__ float4 Es[256];
    __shared__ float4 As[256];

    const int tid = threadIdx.x;
    const float* qb = g_q + (b * LL + by * 64) * HSZ;
    const float* kb = g_k + (b * LL + bx * 64) * HSZ;

    #pragma unroll
    for (int p = 0; p < 16; p++) {
        int e = tid + p * 256;
        int r = e >> 6, h = e & 63;
        qs[h][r] = qb[r * HSZ + h];
        ks[h][r] = kb[r * HSZ + h];
    }
    Es[tid] = ((const float4*)g_E)[(b * LL + bx * 64) * 4 + tid];
    As[tid] = ((const float4*)g_A)[(b * LL + by * 64) * 4 + tid];
    __syncthreads();

    const int m0 = (tid >> 4) * 4;
    const int n0 = (tid & 15) * 4;
    float acc[4][4];
    #pragma unroll
    for (int i = 0; i < 4; i++)
        #pragma unroll
        for (int j = 0; j < 4; j++) acc[i][j] = 0.f;

    #pragma unroll
    for (int h = 0; h < 64; h++) {
        float4 a = *(const float4*)&qs[h][m0];
        float4 v = *(const float4*)&ks[h][n0];
        float am[4] = {a.x, a.y, a.z, a.w};
        float vn[4] = {v.x, v.y, v.z, v.w};
        #pragma unroll
        for (int i = 0; i < 4; i++)
            #pragma unroll
            for (int j = 0; j < 4; j++) acc[i][j] += am[i] * vn[j];
    }
    #pragma unroll
    for (int i = 0; i < 4; i++)
        #pragma unroll
        for (int j = 0; j < 4; j++) Ss[m0 + i][n0 + j] = acc[i][j];
    __syncthreads();

    const int j  = tid >> 2;
    const int oq = tid & 3;
    const bool diag = (bx == by);
    const float4 ev = Es[tid];
    float4* out4 = (float4*)out;
    const size_t bbase = (size_t)b * NP;

    #pragma unroll 4
    for (int sl = 0; sl < 64; sl++) {
        int s  = by * 64 + sl;
        int p0 = ((s * (1025 - s)) >> 1) + bx * 64 - s;
        float  sv = Ss[sl][j];
        float4 av = As[(sl << 2) | oq];
        float4 r  = make_float4(sv + av.x + ev.x, sv + av.y + ev.y,
                                sv + av.z + ev.z, sv + av.w + ev.w);
        if (!diag || j >= sl)
            out4[(bbase + p0) * 4 + tid] = r;
    }
}

extern "C" void kernel_launch(void* const* d_in, const int* in_sizes, int n_in,
                              void* d_out, int out_size)
{
    const float* x  = (const float*)d_in[0];
    const float* Wq = (const float*)d_in[1];
    const float* bq = (const float*)d_in[2];
    const float* Wk = (const float*)d_in[3];
    const float* bk = (const float*)d_in[4];
    const float* Wb = (const float*)d_in[5];
    const float* bb = (const float*)d_in[6];
    float* out = (float*)d_out;

    proj_partial_kernel<<<512, 128>>>(x, Wq, Wk);
    reduce_ae_kernel<<<64, 256>>>(bq, bk, bb, Wb);
    dim3 g2(LL / 64, LL / 64, BN);
    score_scatter_kernel<<<g2, 256>>>(out);
}

// round 11
// speedup vs baseline: 1.0993x; 1.0993x over previous
#include <cuda_runtime.h>

#define BN   4
#define LL   512
#define HH   768
#define HSZ  64
#define NOUT 16
#define NTOK (BN*LL)      // 2048
#define NP   131328       // L*(L+1)/2
#define NKQ  16           // split-K factor
#define KQ   (HH/NKQ)     // 48

// scratch (allocation-free rule: __device__ globals)
__device__ float g_part[NKQ*NTOK*128]; // 16 MB split-K partials [kq][tok][n]
__device__ float g_q[NTOK*HSZ];        // 512 KB
__device__ float g_k[NTOK*HSZ];        // 512 KB
__device__ float g_A[NTOK*NOUT];       // 128 KB
__device__ float g_E[NTOK*NOUT];       // 128 KB

// ---------------------------------------------------------------------------
// Kernel 1: split-K partial GEMM, 8x8 thread tile under a 128-register cap.
// 128-thread blocks; tile = 64 tokens x 128 cols; per-thread 8x8.
// LDS:FMA = 64B:64FMA per thread per kd (co-saturated pipes).
// float4 staging (coalesced, 4x fewer instructions); short operand live
// ranges (one ws float4 live at a time). Grid = 32 x 16 = 512 blocks;
// launch_bounds(128,4) -> 4 blocks/SM -> 16 warps.
// ---------------------------------------------------------------------------
__global__ __launch_bounds__(128, 4) void proj_partial_kernel(
    const float* __restrict__ x,
    const float* __restrict__ Wq,
    const float* __restrict__ Wk)
{
    __shared__ float xs[16][68];     // [d][token]
    __shared__ float ws[16][128];    // [d][n] n<64 -> Wq col else Wk col

    const int tid = threadIdx.x;
    const int tt  = blockIdx.x & 31;           // token tile (64 tokens)
    const int kq  = blockIdx.x >> 5;           // K slice
    const int t0  = tt * 64;
    const int k0  = kq * KQ;

    const int n0 = (tid & 15) * 8;             // 8 cols
    const int m0 = (tid >> 4) * 8;             // 8 tokens

    float acc[8][8];
    #pragma unroll
    for (int i = 0; i < 8; i++)
        #pragma unroll
        for (int j = 0; j < 8; j++) acc[i][j] = 0.f;

    for (int kk = k0; kk < k0 + KQ; kk += 16) {
        // stage x: 64 tok x 16 d = 256 float4 (d4 fastest for coalescing)
        #pragma unroll
        for (int p = 0; p < 2; p++) {
            int e   = tid + p * 128;           // 0..255
            int d4  = e & 3, tok = e >> 2;
            float4 v = *(const float4*)&x[(t0 + tok) * HH + kk + d4 * 4];
            xs[d4 * 4 + 0][tok] = v.x;
            xs[d4 * 4 + 1][tok] = v.y;
            xs[d4 * 4 + 2][tok] = v.z;
            xs[d4 * 4 + 3][tok] = v.w;
        }
        // stage W: 16 d x 32 float4 (16 Wq + 16 Wk per d-row)
        #pragma unroll
        for (int p = 0; p < 4; p++) {
            int e  = tid + p * 128;            // 0..511
            int n4 = e & 31, d = e >> 5;
            float4 v = (n4 < 16)
                ? *(const float4*)&Wq[(kk + d) * HSZ + n4 * 4]
                : *(const float4*)&Wk[(kk + d) * HSZ + (n4 - 16) * 4];
            *(float4*)&ws[d][n4 * 4] = v;
        }
        __syncthreads();
        #pragma unroll
        for (int kd = 0; kd < 16; kd++) {
            float4 a0 = *(const float4*)&xs[kd][m0];
            float4 a1 = *(const float4*)&xs[kd][m0 + 4];
            float am[8] = {a0.x, a0.y, a0.z, a0.w, a1.x, a1.y, a1.z, a1.w};
            #pragma unroll
            for (int jj = 0; jj < 2; jj++) {
                float4 w = *(const float4*)&ws[kd][n0 + jj * 4];
                float wc[4] = {w.x, w.y, w.z, w.w};
                #pragma unroll
                for (int i = 0; i < 8; i++)
                    #pragma unroll
                    for (int c = 0; c < 4; c++)
                        acc[i][jj * 4 + c] += am[i] * wc[c];
            }
        }
        __syncthreads();
    }

    #pragma unroll
    for (int i = 0; i < 8; i++) {
        float* gp = g_part + ((size_t)kq * NTOK + t0 + m0 + i) * 128 + n0;
        *(float4*)&gp[0] = make_float4(acc[i][0], acc[i][1], acc[i][2], acc[i][3]);
        *(float4*)&gp[4] = make_float4(acc[i][4], acc[i][5], acc[i][6], acc[i][7]);
    }
}

// ---------------------------------------------------------------------------
// Kernel 2: reduce split-K partials + bias -> g_q/g_k, then A/E tables.
// A[s,o] = q[s]@Wb[0:64] + bb
// E[e,o] = k[e]@(Wb[64:128]+Wb[192:256]) + q[e]@Wb[128:192]
// ---------------------------------------------------------------------------
__global__ __launch_bounds__(256) void reduce_ae_kernel(
    const float* __restrict__ bq, const float* __restrict__ bk,
    const float* __restrict__ bb, const float* __restrict__ Wb)
{
    __shared__ float Wbs[256 * NOUT];
    __shared__ float sQK[32][132];
    __shared__ float bbs[NOUT];
    __shared__ float bqs[HSZ], bks[HSZ];

    const int tid = threadIdx.x;
    const int t0  = blockIdx.x * 32;

    #pragma unroll
    for (int p = 0; p < 16; p++)
        Wbs[tid + p * 256] = Wb[tid + p * 256];
    if (tid < NOUT) bbs[tid] = bb[tid];
    if (tid < HSZ)  { bqs[tid] = bq[tid]; bks[tid] = bk[tid]; }
    __syncthreads();

    const float4* gp4 = (const float4*)g_part;
    #pragma unroll
    for (int p = 0; p < 4; p++) {
        int e  = tid + p * 256;
        int tok = e >> 5, n4 = e & 31;
        size_t gi = (size_t)(t0 + tok) * 32 + n4;
        float4 v = make_float4(0.f, 0.f, 0.f, 0.f);
        #pragma unroll
        for (int q = 0; q < NKQ; q++) {
            float4 pv = gp4[(size_t)q * NTOK * 32 + gi];
            v.x += pv.x; v.y += pv.y; v.z += pv.z; v.w += pv.w;
        }
        int n = n4 * 4;
        if (n < 64) { v.x += bqs[n]; v.y += bqs[n+1]; v.z += bqs[n+2]; v.w += bqs[n+3]; }
        else        { v.x += bks[n-64]; v.y += bks[n-63]; v.z += bks[n-62]; v.w += bks[n-61]; }
        *(float4*)&sQK[tok][n] = v;
        int tok_g = t0 + tok;
        if (n4 < 16) ((float4*)(g_q + tok_g * HSZ))[n4]      = v;
        else         ((float4*)(g_k + tok_g * HSZ))[n4 - 16] = v;
    }
    __syncthreads();

    // A table: 32 tok x 16 o (warp-uniform)
    #pragma unroll
    for (int p = 0; p < 2; p++) {
        int e2   = tid + p * 256;
        int tokL = e2 >> 4;
        int o    = e2 & 15;
        float a = bbs[o];
        #pragma unroll 8
        for (int h = 0; h < 64; h++)
            a += sQK[tokL][h] * Wbs[h * NOUT + o];
        g_A[(t0 + tokL) * NOUT + o] = a;
    }
    // E table
    #pragma unroll
    for (int p = 0; p < 2; p++) {
        int e2   = tid + p * 256;
        int tokL = e2 >> 4;
        int o    = e2 & 15;
        float a = 0.f;
        #pragma unroll 8
        for (int h = 0; h < 64; h++) {
            a += sQK[tokL][64 + h] * (Wbs[(64 + h) * NOUT + o] + Wbs[(192 + h) * NOUT + o]);
            a += sQK[tokL][h]      *  Wbs[(128 + h) * NOUT + o];
        }
        g_E[(t0 + tokL) * NOUT + o] = a;
    }
}

// ---------------------------------------------------------------------------
// Kernel 3: FUSED score + scatter (unchanged). One block per 64x64 tile;
// below-diagonal tiles exit; output streamed straight from shared.
// ---------------------------------------------------------------------------
__global__ __launch_bounds__(256) void score_scatter_kernel(float* __restrict__ out)
{
    const int bx = blockIdx.x;   // e tile
    const int by = blockIdx.y;   // s tile
    if (by > bx) return;
    const int b  = blockIdx.z;

    __shared__ float  qs[64][68];
    __shared__ float  ks[64][68];
    __shared__ float  Ss[64][65];
    __shared__ float4 Es[256];
    __shared__ float4 As[256];

    const int tid = threadIdx.x;
    const float* qb = g_q + (b * LL + by * 64) * HSZ;
    const float* kb = g_k + (b * LL + bx * 64) * HSZ;

    #pragma unroll
    for (int p = 0; p < 16; p++) {
        int e = tid + p * 256;
        int r = e >> 6, h = e & 63;
        qs[h][r] = qb[r * HSZ + h];
        ks[h][r] = kb[r * HSZ + h];
    }
    Es[tid] = ((const float4*)g_E)[(b * LL + bx * 64) * 4 + tid];
    As[tid] = ((const float4*)g_A)[(b * LL + by * 64) * 4 + tid];
    __syncthreads();

    const int m0 = (tid >> 4) * 4;
    const int n0 = (tid & 15) * 4;
    float acc[4][4];
    #pragma unroll
    for (int i = 0; i < 4; i++)
        #pragma unroll
        for (int j = 0; j < 4; j++) acc[i][j] = 0.f;

    #pragma unroll
    for (int h = 0; h < 64; h++) {
        float4 a = *(const float4*)&qs[h][m0];
        float4 v = *(const float4*)&ks[h][n0];
        float am[4] = {a.x, a.y, a.z, a.w};
        float vn[4] = {v.x, v.y, v.z, v.w};
        #pragma unroll
        for (int i = 0; i < 4; i++)
            #pragma unroll
            for (int j = 0; j < 4; j++) acc[i][j] += am[i] * vn[j];
    }
    #pragma unroll
    for (int i = 0; i < 4; i++)
        #pragma unroll
        for (int j = 0; j < 4; j++) Ss[m0 + i][n0 + j] = acc[i][j];
    __syncthreads();

    const int j  = tid >> 2;
    const int oq = tid & 3;
    const bool diag = (bx == by);
    const float4 ev = Es[tid];
    float4* out4 = (float4*)out;
    const size_t bbase = (size_t)b * NP;

    #pragma unroll 4
    for (int sl = 0; sl < 64; sl++) {
        int s  = by * 64 + sl;
        int p0 = ((s * (1025 - s)) >> 1) + bx * 64 - s;
        float  sv = Ss[sl][j];
        float4 av = As[(sl << 2) | oq];
        float4 r  = make_float4(sv + av.x + ev.x, sv + av.y + ev.y,
                                sv + av.z + ev.z, sv + av.w + ev.w);
        if (!diag || j >= sl)
            out4[(bbase + p0) * 4 + tid] = r;
    }
}

extern "C" void kernel_launch(void* const* d_in, const int* in_sizes, int n_in,
                              void* d_out, int out_size)
{
    const float* x  = (const float*)d_in[0];
    const float* Wq = (const float*)d_in[1];
    const float* bq = (const float*)d_in[2];
    const float* Wk = (const float*)d_in[3];
    const float* bk = (const float*)d_in[4];
    const float* Wb = (const float*)d_in[5];
    const float* bb = (const float*)d_in[6];
    float* out = (float*)d_out;

    proj_partial_kernel<<<512, 128>>>(x, Wq, Wk);
    reduce_ae_kernel<<<64, 256>>>(bq, bk, bb, Wb);
    dim3 g2(LL / 64, LL / 64, BN);
    score_scatter_kernel<<<g2, 256>>>(out);
}